// round 10
// baseline (speedup 1.0000x reference)
#include <cuda_runtime.h>
#include <cuda_fp16.h>
#include <cstdint>
#include <cstddef>

// Problem shape (fixed)
#define Bc 2
#define Hc 16
#define Sc 2048
#define Dc 64
#define NELEM  (Bc * Hc * Sc * Dc)   // 4194304
#define NELEM2 (NELEM / 2)

// Tiling
#define BM 128            // q rows per CTA
#define BK 64             // keys per tile
#define NT (Sc / BK)      // 32 tiles
#define PH 72             // fp16 smem pitch (halfs); 144B rows -> conflict-free ldmatrix

// SMEM layout (bytes)
#define SM_Q   0
#define SMQB   (BM * PH * 2)          // 18432
#define KVB    (BK * PH * 2)          // 9216 (one K or V tile)
#define STB    (2 * KVB)              // 18432 per stage (K + V)
#define NSTG   3
#define SM_TOT (SMQB + NSTG * STB)    // 73728

// fp16 scratch (pre-converted inputs)
__device__ __align__(16) __half2 QH[NELEM2];
__device__ __align__(16) __half2 KH[NELEM2];
__device__ __align__(16) __half2 VH[NELEM2];

__global__ void cvt_f2h(const float2* __restrict__ q,
                        const float2* __restrict__ k,
                        const float2* __restrict__ v)
{
    int i = blockIdx.x * 256 + threadIdx.x;
    float2 a = q[i]; QH[i] = __floats2half2_rn(a.x, a.y);
    float2 b = k[i]; KH[i] = __floats2half2_rn(b.x, b.y);
    float2 c = v[i]; VH[i] = __floats2half2_rn(c.x, c.y);
}

static __device__ __forceinline__ uint32_t smem_u32(const void* p) {
    uint32_t a;
    asm("{ .reg .u64 t; cvta.to.shared.u64 t, %1; cvt.u32.u64 %0, t; }"
        : "=r"(a) : "l"(p));
    return a;
}
static __device__ __forceinline__ void mma_f16(float c[4],
                                               uint32_t a0, uint32_t a1, uint32_t a2, uint32_t a3,
                                               uint32_t b0, uint32_t b1) {
    asm volatile(
        "mma.sync.aligned.m16n8k16.row.col.f32.f16.f16.f32 "
        "{%0,%1,%2,%3}, {%4,%5,%6,%7}, {%8,%9}, {%0,%1,%2,%3};"
        : "+f"(c[0]), "+f"(c[1]), "+f"(c[2]), "+f"(c[3])
        : "r"(a0), "r"(a1), "r"(a2), "r"(a3), "r"(b0), "r"(b1));
}
static __device__ __forceinline__ void ldsm4(uint32_t& r0, uint32_t& r1,
                                             uint32_t& r2, uint32_t& r3, uint32_t a) {
    asm volatile("ldmatrix.sync.aligned.m8n8.x4.shared.b16 {%0,%1,%2,%3}, [%4];"
                 : "=r"(r0), "=r"(r1), "=r"(r2), "=r"(r3) : "r"(a));
}
static __device__ __forceinline__ void ldsm4t(uint32_t& r0, uint32_t& r1,
                                              uint32_t& r2, uint32_t& r3, uint32_t a) {
    asm volatile("ldmatrix.sync.aligned.m8n8.x4.trans.shared.b16 {%0,%1,%2,%3}, [%4];"
                 : "=r"(r0), "=r"(r1), "=r"(r2), "=r"(r3) : "r"(a));
}
static __device__ __forceinline__ void cp16(uint32_t dst, const void* src) {
    asm volatile("cp.async.cg.shared.global [%0], [%1], 16;"
                 :: "r"(dst), "l"(src) : "memory");
}

__global__ __launch_bounds__(256, 2)
void fra_f16_kernel(const float* __restrict__ mask, float* __restrict__ o)
{
    extern __shared__ char smem[];
    const uint32_t sb = smem_u32(smem);
    const int tid  = threadIdx.x;
    const int lane = tid & 31;
    const int wid  = tid >> 5;
    const int gid  = lane >> 2;
    const int tig  = lane & 3;
    const int mbase = wid * 16;            // warp's 16-row strip
    const int bh = blockIdx.y;
    const int q0 = blockIdx.x * BM;

    const __half* qh = (const __half*)QH + (size_t)bh * Sc * Dc;
    const __half* kh = (const __half*)KH + (size_t)bh * Sc * Dc;
    const __half* vh = (const __half*)VH + (size_t)bh * Sc * Dc;
    const float*  mg = mask + (size_t)bh * Sc * Sc;
    float*        og = o    + (size_t)bh * Sc * Dc;

    // ---- prologue: cp.async Q + tile0 (group A), tile1 (group B) ----
    {
        #pragma unroll
        for (int i = 0; i < 4; i++) {
            int fi = tid + i * 256;
            int r = fi >> 3, c8 = fi & 7;
            cp16(sb + SM_Q + (uint32_t)(r * PH + c8 * 8) * 2,
                 qh + (size_t)(q0 + r) * Dc + c8 * 8);
        }
        #pragma unroll
        for (int i = 0; i < 2; i++) {
            int fi = tid + i * 256;
            int r = fi >> 3, c8 = fi & 7;
            cp16(sb + SMQB + (uint32_t)(r * PH + c8 * 8) * 2,
                 kh + (size_t)r * Dc + c8 * 8);
            cp16(sb + SMQB + KVB + (uint32_t)(r * PH + c8 * 8) * 2,
                 vh + (size_t)r * Dc + c8 * 8);
        }
        asm volatile("cp.async.commit_group;" ::: "memory");
        #pragma unroll
        for (int i = 0; i < 2; i++) {
            int fi = tid + i * 256;
            int r = fi >> 3, c8 = fi & 7;
            cp16(sb + SMQB + STB + (uint32_t)(r * PH + c8 * 8) * 2,
                 kh + (size_t)(BK + r) * Dc + c8 * 8);
            cp16(sb + SMQB + STB + KVB + (uint32_t)(r * PH + c8 * 8) * 2,
                 vh + (size_t)(BK + r) * Dc + c8 * 8);
        }
        asm volatile("cp.async.commit_group;" ::: "memory");
    }

    // per-lane fragment address components
    const int qrow  = (lane & 7) + 8 * ((lane >> 3) & 1);   // A / V-trans row pattern
    const int qcol8 = 8 * (lane >> 4);
    const int krow  = (lane & 7) + 8 * (lane >> 4);          // K B-frag row pattern
    const int kcolb = 8 * ((lane >> 3) & 1);
    const uint32_t aQ = sb + SM_Q + (uint32_t)((mbase + qrow) * PH + qcol8) * 2;

    float oacc[8][4];
    #pragma unroll
    for (int d = 0; d < 8; d++)
        #pragma unroll
        for (int r = 0; r < 4; r++) oacc[d][r] = 0.0f;
    float racc0 = 0.0f, racc1 = 0.0f;

    const float* mr0 = mg + (size_t)(q0 + mbase + gid) * Sc + 2 * tig;
    const float* mr1 = mr0 + (size_t)8 * Sc;

    // ---- mask register double-buffer: preload tile 0 (overlaps cp.async) ----
    float2 mc0[8], mc1[8];
    #pragma unroll
    for (int j = 0; j < 8; j++) {
        mc0[j] = *(const float2*)(mr0 + 8 * j);
        mc1[j] = *(const float2*)(mr1 + 8 * j);
    }

    for (int tt = 0; tt < NT; tt++) {
        const int t = tt * BK;
        // issue tile tt+2 into stage (tt+2)%3 (freed by end-barrier of iter tt-1)
        if (tt + 2 < NT) {
            const uint32_t stb = sb + SMQB + (uint32_t)((tt + 2) % NSTG) * STB;
            #pragma unroll
            for (int i = 0; i < 2; i++) {
                int fi = tid + i * 256;
                int r = fi >> 3, c8 = fi & 7;
                cp16(stb + (uint32_t)(r * PH + c8 * 8) * 2,
                     kh + (size_t)(t + 2 * BK + r) * Dc + c8 * 8);
                cp16(stb + KVB + (uint32_t)(r * PH + c8 * 8) * 2,
                     vh + (size_t)(t + 2 * BK + r) * Dc + c8 * 8);
            }
            asm volatile("cp.async.commit_group;" ::: "memory");
            asm volatile("cp.async.wait_group 2;" ::: "memory");
        } else if (tt + 1 < NT) {
            asm volatile("cp.async.wait_group 1;" ::: "memory");
        } else {
            asm volatile("cp.async.wait_group 0;" ::: "memory");
        }
        __syncthreads();   // tile tt visible to all warps

        const uint32_t kbs = sb + SMQB + (uint32_t)(tt % NSTG) * STB;
        const uint32_t vbs = kbs + KVB;

        // ---- GEMM1: S(16x64) = Q @ K^T, fp16 m16n8k16, 4 k-steps ----
        float sacc[8][4];
        #pragma unroll
        for (int j = 0; j < 8; j++)
            #pragma unroll
            for (int r = 0; r < 4; r++) sacc[j][r] = 0.0f;

        #pragma unroll
        for (int kk = 0; kk < 4; kk++) {
            uint32_t a0, a1, a2, a3;
            ldsm4(a0, a1, a2, a3, aQ + (uint32_t)kk * 32);
            #pragma unroll
            for (int p = 0; p < 4; p++) {
                uint32_t b0, b1, b2, b3;
                ldsm4(b0, b1, b2, b3,
                      kbs + (uint32_t)((16 * p + krow) * PH + kk * 16 + kcolb) * 2);
                mma_f16(sacc[2 * p],     a0, a1, a2, a3, b0, b1);
                mma_f16(sacc[2 * p + 1], a0, a1, a2, a3, b2, b3);
            }
        }

        // ---- mask (from regs) + abs-sum + pack P-frags, then reload mask regs ----
        uint32_t ph[8][2];
        #pragma unroll
        for (int j = 0; j < 8; j++) {
            float s0 = sacc[j][0] * mc0[j].x;
            float s1 = sacc[j][1] * mc0[j].y;
            float s2 = sacc[j][2] * mc1[j].x;
            float s3 = sacc[j][3] * mc1[j].y;
            racc0 += fabsf(s0) + fabsf(s1);
            racc1 += fabsf(s2) + fabsf(s3);
            __half2 p0 = __floats2half2_rn(s0, s1);
            __half2 p1 = __floats2half2_rn(s2, s3);
            ph[j][0] = *(uint32_t*)&p0;
            ph[j][1] = *(uint32_t*)&p1;
        }
        if (tt + 1 < NT) {
            #pragma unroll
            for (int j = 0; j < 8; j++) {
                mc0[j] = *(const float2*)(mr0 + t + BK + 8 * j);
                mc1[j] = *(const float2*)(mr1 + t + BK + 8 * j);
            }
        }

        // ---- GEMM2: O(16x64) += P @ V, B-frags via ldmatrix.trans on V ----
        #pragma unroll
        for (int kk = 0; kk < 4; kk++) {
            uint32_t a0 = ph[2 * kk][0];
            uint32_t a1 = ph[2 * kk][1];
            uint32_t a2 = ph[2 * kk + 1][0];
            uint32_t a3 = ph[2 * kk + 1][1];
            #pragma unroll
            for (int p = 0; p < 4; p++) {
                uint32_t b0, b1, b2, b3;
                ldsm4t(b0, b1, b2, b3,
                       vbs + (uint32_t)((16 * kk + qrow) * PH + 16 * p + qcol8) * 2);
                mma_f16(oacc[2 * p],     a0, a1, a2, a3, b0, b1);
                mma_f16(oacc[2 * p + 1], a0, a1, a2, a3, b2, b3);
            }
        }
        __syncthreads();   // stage (tt)%3 free for reuse at iter tt+1's issue
    }

    // ---- warp-local row abs-sums (warp owns full rows) ----
    racc0 += __shfl_xor_sync(0xffffffffu, racc0, 1);
    racc0 += __shfl_xor_sync(0xffffffffu, racc0, 2);
    racc1 += __shfl_xor_sync(0xffffffffu, racc1, 1);
    racc1 += __shfl_xor_sync(0xffffffffu, racc1, 2);
    const float rinv0 = 1.0f / fmaxf(racc0, 1.0f);
    const float rinv1 = 1.0f / fmaxf(racc1, 1.0f);

    float* or0 = og + (size_t)(q0 + mbase + gid) * Dc;
    float* or1 = or0 + (size_t)8 * Dc;
    #pragma unroll
    for (int db = 0; db < 8; db++) {
        const int col = 8 * db + 2 * tig;
        float2 y0, y1;
        y0.x = oacc[db][0] * rinv0; y0.y = oacc[db][1] * rinv0;
        y1.x = oacc[db][2] * rinv1; y1.y = oacc[db][3] * rinv1;
        *(float2*)(or0 + col) = y0;
        *(float2*)(or1 + col) = y1;
    }
}

extern "C" void kernel_launch(void* const* d_in, const int* in_sizes, int n_in,
                              void* d_out, int out_size)
{
    (void)in_sizes; (void)n_in; (void)out_size;
    const float* q    = (const float*)d_in[0];
    const float* k    = (const float*)d_in[1];
    const float* v    = (const float*)d_in[2];
    const float* mask = (const float*)d_in[3];
    float* o = (float*)d_out;

    // pre-convert q/k/v to fp16 scratch
    cvt_f2h<<<NELEM2 / 256, 256>>>((const float2*)q, (const float2*)k, (const float2*)v);

    cudaFuncSetAttribute(fra_f16_kernel,
                         cudaFuncAttributeMaxDynamicSharedMemorySize, SM_TOT);
    dim3 grid(Sc / BM, Bc * Hc);   // (16, 32)
    fra_f16_kernel<<<grid, 256, SM_TOT>>>(mask, o);
}

// round 11
// speedup vs baseline: 1.1172x; 1.1172x over previous
#include <cuda_runtime.h>
#include <cuda_fp16.h>
#include <cstdint>
#include <cstddef>

// Problem shape (fixed)
#define Bc 2
#define Hc 16
#define Sc 2048
#define Dc 64
#define NELEM  (Bc * Hc * Sc * Dc)   // 4194304
#define NELEM2 (NELEM / 2)

// Tiling
#define BM 128            // q rows per CTA
#define BK 64             // keys per tile
#define NT (Sc / BK)      // 32 tiles
#define PH 72             // fp16 smem pitch (halfs); 144B rows -> conflict-free ldmatrix

// SMEM layout (bytes)
#define SM_Q   0
#define SMQB   (BM * PH * 2)          // 18432
#define KVB    (BK * PH * 2)          // 9216 (one K or V tile)
#define STB    (2 * KVB)              // 18432 per stage (K + V)
#define NSTG   4
#define SM_TOT (SMQB + NSTG * STB)    // 92160

// fp16 scratch (pre-converted inputs)
__device__ __align__(16) __half2 QH[NELEM2];
__device__ __align__(16) __half2 KH[NELEM2];
__device__ __align__(16) __half2 VH[NELEM2];

__global__ void cvt_f2h(const float2* __restrict__ q,
                        const float2* __restrict__ k,
                        const float2* __restrict__ v)
{
    int i = blockIdx.x * 256 + threadIdx.x;
    float2 a = q[i]; QH[i] = __floats2half2_rn(a.x, a.y);
    float2 b = k[i]; KH[i] = __floats2half2_rn(b.x, b.y);
    float2 c = v[i]; VH[i] = __floats2half2_rn(c.x, c.y);
}

static __device__ __forceinline__ uint32_t smem_u32(const void* p) {
    uint32_t a;
    asm("{ .reg .u64 t; cvta.to.shared.u64 t, %1; cvt.u32.u64 %0, t; }"
        : "=r"(a) : "l"(p));
    return a;
}
static __device__ __forceinline__ void mma_f16(float c[4],
                                               uint32_t a0, uint32_t a1, uint32_t a2, uint32_t a3,
                                               uint32_t b0, uint32_t b1) {
    asm volatile(
        "mma.sync.aligned.m16n8k16.row.col.f32.f16.f16.f32 "
        "{%0,%1,%2,%3}, {%4,%5,%6,%7}, {%8,%9}, {%0,%1,%2,%3};"
        : "+f"(c[0]), "+f"(c[1]), "+f"(c[2]), "+f"(c[3])
        : "r"(a0), "r"(a1), "r"(a2), "r"(a3), "r"(b0), "r"(b1));
}
static __device__ __forceinline__ void ldsm4(uint32_t& r0, uint32_t& r1,
                                             uint32_t& r2, uint32_t& r3, uint32_t a) {
    asm volatile("ldmatrix.sync.aligned.m8n8.x4.shared.b16 {%0,%1,%2,%3}, [%4];"
                 : "=r"(r0), "=r"(r1), "=r"(r2), "=r"(r3) : "r"(a));
}
static __device__ __forceinline__ void ldsm4t(uint32_t& r0, uint32_t& r1,
                                              uint32_t& r2, uint32_t& r3, uint32_t a) {
    asm volatile("ldmatrix.sync.aligned.m8n8.x4.trans.shared.b16 {%0,%1,%2,%3}, [%4];"
                 : "=r"(r0), "=r"(r1), "=r"(r2), "=r"(r3) : "r"(a));
}
static __device__ __forceinline__ void cp16(uint32_t dst, const void* src) {
    asm volatile("cp.async.cg.shared.global [%0], [%1], 16;"
                 :: "r"(dst), "l"(src) : "memory");
}

__global__ __launch_bounds__(256, 2)
void fra_f16_kernel(const float* __restrict__ mask, float* __restrict__ o)
{
    extern __shared__ char smem[];
    const uint32_t sb = smem_u32(smem);
    const int tid  = threadIdx.x;
    const int lane = tid & 31;
    const int wid  = tid >> 5;
    const int gid  = lane >> 2;
    const int tig  = lane & 3;
    const int mbase = wid * 16;            // warp's 16-row strip
    const int bh = blockIdx.y;
    const int q0 = blockIdx.x * BM;

    const __half* qh = (const __half*)QH + (size_t)bh * Sc * Dc;
    const __half* kh = (const __half*)KH + (size_t)bh * Sc * Dc;
    const __half* vh = (const __half*)VH + (size_t)bh * Sc * Dc;
    const float*  mg = mask + (size_t)bh * Sc * Sc;
    float*        og = o    + (size_t)bh * Sc * Dc;

    // ---- prologue: cp.async Q + tile0 (group A), tile1 (group B) ----
    {
        #pragma unroll
        for (int i = 0; i < 4; i++) {
            int fi = tid + i * 256;
            int r = fi >> 3, c8 = fi & 7;
            cp16(sb + SM_Q + (uint32_t)(r * PH + c8 * 8) * 2,
                 qh + (size_t)(q0 + r) * Dc + c8 * 8);
        }
        #pragma unroll
        for (int i = 0; i < 2; i++) {
            int fi = tid + i * 256;
            int r = fi >> 3, c8 = fi & 7;
            cp16(sb + SMQB + (uint32_t)(r * PH + c8 * 8) * 2,
                 kh + (size_t)r * Dc + c8 * 8);
            cp16(sb + SMQB + KVB + (uint32_t)(r * PH + c8 * 8) * 2,
                 vh + (size_t)r * Dc + c8 * 8);
        }
        asm volatile("cp.async.commit_group;" ::: "memory");
        #pragma unroll
        for (int i = 0; i < 2; i++) {
            int fi = tid + i * 256;
            int r = fi >> 3, c8 = fi & 7;
            cp16(sb + SMQB + STB + (uint32_t)(r * PH + c8 * 8) * 2,
                 kh + (size_t)(BK + r) * Dc + c8 * 8);
            cp16(sb + SMQB + STB + KVB + (uint32_t)(r * PH + c8 * 8) * 2,
                 vh + (size_t)(BK + r) * Dc + c8 * 8);
        }
        asm volatile("cp.async.commit_group;" ::: "memory");
    }

    // per-lane fragment address components
    const int qrow  = (lane & 7) + 8 * ((lane >> 3) & 1);   // A / V-trans row pattern
    const int qcol8 = 8 * (lane >> 4);
    const int krow  = (lane & 7) + 8 * (lane >> 4);          // K B-frag row pattern
    const int kcolb = 8 * ((lane >> 3) & 1);
    const uint32_t aQ = sb + SM_Q + (uint32_t)((mbase + qrow) * PH + qcol8) * 2;

    float oacc[8][4];
    #pragma unroll
    for (int d = 0; d < 8; d++)
        #pragma unroll
        for (int r = 0; r < 4; r++) oacc[d][r] = 0.0f;
    float racc0 = 0.0f, racc1 = 0.0f;

    const float* mr0 = mg + (size_t)(q0 + mbase + gid) * Sc + 2 * tig;
    const float* mr1 = mr0 + (size_t)8 * Sc;

    for (int tt = 0; tt < NT; tt++) {
        const int t = tt * BK;
        // issue tile tt+2 into stage (tt+2)%4
        if (tt + 2 < NT) {
            const uint32_t stb = sb + SMQB + (uint32_t)((tt + 2) % NSTG) * STB;
            #pragma unroll
            for (int i = 0; i < 2; i++) {
                int fi = tid + i * 256;
                int r = fi >> 3, c8 = fi & 7;
                cp16(stb + (uint32_t)(r * PH + c8 * 8) * 2,
                     kh + (size_t)(t + 2 * BK + r) * Dc + c8 * 8);
                cp16(stb + KVB + (uint32_t)(r * PH + c8 * 8) * 2,
                     vh + (size_t)(t + 2 * BK + r) * Dc + c8 * 8);
            }
            asm volatile("cp.async.commit_group;" ::: "memory");
            asm volatile("cp.async.wait_group 2;" ::: "memory");
        } else if (tt + 1 < NT) {
            asm volatile("cp.async.wait_group 1;" ::: "memory");
        } else {
            asm volatile("cp.async.wait_group 0;" ::: "memory");
        }
        // Single barrier per tile: makes tile tt visible AND (because a stage
        // read at iter tt is only re-written at iter tt+2) protects stage reuse.
        __syncthreads();

        const uint32_t kbs = sb + SMQB + (uint32_t)(tt % NSTG) * STB;
        const uint32_t vbs = kbs + KVB;

        // ---- issue this tile's mask loads early (latency under GEMM1) ----
        float2 mc0[8], mc1[8];
        #pragma unroll
        for (int j = 0; j < 8; j++) {
            mc0[j] = *(const float2*)(mr0 + t + 8 * j);
            mc1[j] = *(const float2*)(mr1 + t + 8 * j);
        }

        // ---- GEMM1: S(16x64) = Q @ K^T, fp16 m16n8k16, 4 k-steps ----
        float sacc[8][4];
        #pragma unroll
        for (int j = 0; j < 8; j++)
            #pragma unroll
            for (int r = 0; r < 4; r++) sacc[j][r] = 0.0f;

        #pragma unroll
        for (int kk = 0; kk < 4; kk++) {
            uint32_t a0, a1, a2, a3;
            ldsm4(a0, a1, a2, a3, aQ + (uint32_t)kk * 32);
            #pragma unroll
            for (int p = 0; p < 4; p++) {
                uint32_t b0, b1, b2, b3;
                ldsm4(b0, b1, b2, b3,
                      kbs + (uint32_t)((16 * p + krow) * PH + kk * 16 + kcolb) * 2);
                mma_f16(sacc[2 * p],     a0, a1, a2, a3, b0, b1);
                mma_f16(sacc[2 * p + 1], a0, a1, a2, a3, b2, b3);
            }
        }

        // ---- mask (regs) + abs-sum + pack P-frags ----
        uint32_t ph[8][2];
        #pragma unroll
        for (int j = 0; j < 8; j++) {
            float s0 = sacc[j][0] * mc0[j].x;
            float s1 = sacc[j][1] * mc0[j].y;
            float s2 = sacc[j][2] * mc1[j].x;
            float s3 = sacc[j][3] * mc1[j].y;
            racc0 += fabsf(s0) + fabsf(s1);
            racc1 += fabsf(s2) + fabsf(s3);
            __half2 p0 = __floats2half2_rn(s0, s1);
            __half2 p1 = __floats2half2_rn(s2, s3);
            ph[j][0] = *(uint32_t*)&p0;
            ph[j][1] = *(uint32_t*)&p1;
        }

        // ---- GEMM2: O(16x64) += P @ V, B-frags via ldmatrix.trans on V ----
        #pragma unroll
        for (int kk = 0; kk < 4; kk++) {
            uint32_t a0 = ph[2 * kk][0];
            uint32_t a1 = ph[2 * kk][1];
            uint32_t a2 = ph[2 * kk + 1][0];
            uint32_t a3 = ph[2 * kk + 1][1];
            #pragma unroll
            for (int p = 0; p < 4; p++) {
                uint32_t b0, b1, b2, b3;
                ldsm4t(b0, b1, b2, b3,
                       vbs + (uint32_t)((16 * kk + qrow) * PH + 16 * p + qcol8) * 2);
                mma_f16(oacc[2 * p],     a0, a1, a2, a3, b0, b1);
                mma_f16(oacc[2 * p + 1], a0, a1, a2, a3, b2, b3);
            }
        }
        // no bottom barrier: stage reuse is protected by the next two top barriers
    }

    // ---- warp-local row abs-sums (warp owns full rows) ----
    racc0 += __shfl_xor_sync(0xffffffffu, racc0, 1);
    racc0 += __shfl_xor_sync(0xffffffffu, racc0, 2);
    racc1 += __shfl_xor_sync(0xffffffffu, racc1, 1);
    racc1 += __shfl_xor_sync(0xffffffffu, racc1, 2);
    const float rinv0 = 1.0f / fmaxf(racc0, 1.0f);
    const float rinv1 = 1.0f / fmaxf(racc1, 1.0f);

    float* or0 = og + (size_t)(q0 + mbase + gid) * Dc;
    float* or1 = or0 + (size_t)8 * Dc;
    #pragma unroll
    for (int db = 0; db < 8; db++) {
        const int col = 8 * db + 2 * tig;
        float2 y0, y1;
        y0.x = oacc[db][0] * rinv0; y0.y = oacc[db][1] * rinv0;
        y1.x = oacc[db][2] * rinv1; y1.y = oacc[db][3] * rinv1;
        *(float2*)(or0 + col) = y0;
        *(float2*)(or1 + col) = y1;
    }
}

extern "C" void kernel_launch(void* const* d_in, const int* in_sizes, int n_in,
                              void* d_out, int out_size)
{
    (void)in_sizes; (void)n_in; (void)out_size;
    const float* q    = (const float*)d_in[0];
    const float* k    = (const float*)d_in[1];
    const float* v    = (const float*)d_in[2];
    const float* mask = (const float*)d_in[3];
    float* o = (float*)d_out;

    // pre-convert q/k/v to fp16 scratch
    cvt_f2h<<<NELEM2 / 256, 256>>>((const float2*)q, (const float2*)k, (const float2*)v);

    cudaFuncSetAttribute(fra_f16_kernel,
                         cudaFuncAttributeMaxDynamicSharedMemorySize, SM_TOT);
    dim3 grid(Sc / BM, Bc * Hc);   // (16, 32)
    fra_f16_kernel<<<grid, 256, SM_TOT>>>(mask, o);
}